// round 7
// baseline (speedup 1.0000x reference)
#include <cuda_runtime.h>
#include <cstddef>

// Problem constants (fixed by the dataset)
#define Fk   51
#define HOo  512
#define WOo  512
#define CC   3
#define HIN  562   // HO + F - 1
#define WIN  562
#define BB   2
#define HW   (HOo * WOo)

// Tiling: each thread computes 2 x-cols × 2 y-rows. Block = 32×4 threads
// -> output tile 64 wide × 8 tall.
#define TXX  32
#define WYY  4
#define RXX  2
#define RYY  2
#define TW   (TXX * RXX)        // 64 output cols per block
#define TYY  (WYY * RYY)        // 8 output rows per block
#define TROWS (TYY + Fk - 1)    // 58 input rows
#define TCOLS 114               // cols 0..113 used (2*31 + 51 = 113); even stride
#define TILE_ELEMS (TROWS * TCOLS)

#define NPAIR 13                // tap pairs per half (2 halves x 13 pairs = 26 pairs = taps 0..51)

typedef unsigned long long u64;

// ---- packed f32x2 helpers (Blackwell FFMA2 path) ----
__device__ __forceinline__ u64 pack2(float lo, float hi) {
    u64 r;
    asm("mov.b64 %0, {%1, %2};" : "=l"(r) : "f"(lo), "f"(hi));
    return r;
}
__device__ __forceinline__ void unpack2(u64 v, float& lo, float& hi) {
    asm("mov.b64 {%0, %1}, %2;" : "=f"(lo), "=f"(hi) : "l"(v));
}
__device__ __forceinline__ void ffma2(u64& d, u64 a, u64 b) {
    asm("fma.rn.f32x2 %0, %1, %2, %0;" : "+l"(d) : "l"(a), "l"(b));
}
__device__ __forceinline__ float2 ldg2(const float* p) {
    return __ldg(reinterpret_cast<const float2*>(p));
}

__global__ __launch_bounds__(TXX * WYY, 2)
void sepconv_kernel(const float* __restrict__ inp,
                    const float* __restrict__ vert,
                    const float* __restrict__ horz,
                    float* __restrict__ out)
{
    __shared__ __align__(16) float tile[TILE_ELEMS];

    const int b   = blockIdx.z;
    const int x0  = blockIdx.x * TW;
    const int y0  = blockIdx.y * TYY;
    const int tx  = threadIdx.x;
    const int ty  = threadIdx.y;
    const int tid = ty * TXX + tx;

    const int xA = x0 + 2 * tx;      // thread's even column (and xA+1)
    const int yA = y0 + ty * RYY;    // thread's rows yA, yA+1

    // filter bases: layout [b, tap, y, x]
    const float* h_base = horz + (size_t)b * Fk * HW + (size_t)yA * WOo + xA;
    const float* v_base = vert + (size_t)b * Fk * HW + (size_t)yA * WOo + xA;

    #pragma unroll 1
    for (int c = 0; c < CC; ++c) {
        // ---- Cooperative input tile load (fully in-bounds: max col 113 -> x 561) ----
        const float* gsrc = inp + (((size_t)b * CC + c) * HIN + y0) * WIN + x0;
        __syncthreads();   // protect prior iteration's tile reads
        #pragma unroll 1
        for (int idx = tid; idx < TILE_ELEMS; idx += TXX * WYY) {
            int r   = idx / TCOLS;
            int col = idx - r * TCOLS;
            tile[idx] = gsrc[(size_t)r * WIN + col];
        }
        __syncthreads();

        u64 acc2[RXX][RYY];   // [col][yy] packed {even-chain, odd-chain} partials
        acc2[0][0] = acc2[0][1] = acc2[1][0] = acc2[1][1] = 0ULL;

        #pragma unroll 1
        for (int half = 0; half < 2; ++half) {
            const int T0 = half * NPAIR;   // global pair index offset (0 or 13)

            // ---- Pack this half's horizontal taps for both columns ----
            // col A (x=xA):   pair T -> {h[2T],   h[2T+1]}   (h[51] := 0)
            // col B (x=xA+1): pair T -> {h[2T-1], h[2T]}     (h[-1] := 0)
            // Each h LDG.64 fetches {h[j,y,xA], h[j,y,xA+1]} for both columns.
            u64 hA2[RYY][NPAIR], hB2[RYY][NPAIR];
            #pragma unroll
            for (int yy = 0; yy < RYY; ++yy) {
                const float* hp = h_base + (size_t)yy * WOo;
                #pragma unroll
                for (int tl = 0; tl < NPAIR; ++tl) {
                    int T = T0 + tl;
                    float2 gm = (2 * T - 1 >= 0) ? ldg2(hp + (size_t)(2 * T - 1) * HW)
                                                 : make_float2(0.f, 0.f);
                    float2 gc = ldg2(hp + (size_t)(2 * T) * HW);        // 2T <= 50 always
                    float2 gp = (2 * T + 1 < Fk) ? ldg2(hp + (size_t)(2 * T + 1) * HW)
                                                 : make_float2(0.f, 0.f);
                    hA2[yy][tl] = pack2(gc.x, gp.x);
                    hB2[yy][tl] = pack2(gm.y, gc.y);
                }
            }

            const float* rowbase = tile + (ty * RYY) * TCOLS + 2 * tx + 2 * T0;

            #pragma unroll 1
            for (int rr = 0; rr < Fk + RYY - 1; ++rr) {   // 52 input rows
                // 13 aligned LDS.64 input pairs for this row / tap-half
                const u64* rp = reinterpret_cast<const u64*>(rowbase + rr * TCOLS);
                u64 in2[NPAIR];
                #pragma unroll
                for (int tl = 0; tl < NPAIR; ++tl) in2[tl] = rp[tl];

                // vertical weights for both columns (float2), predicated at edges
                float2 v0 = (rr <= Fk - 1) ? ldg2(v_base + (size_t)rr * HW)
                                           : make_float2(0.f, 0.f);
                float2 v1 = (rr >= 1)      ? ldg2(v_base + (size_t)(rr - 1) * HW + WOo)
                                           : make_float2(0.f, 0.f);

                // 4 packed dot products; one chain each (4-way ILP)
                u64 sA0 = 0ULL, sA1 = 0ULL, sB0 = 0ULL, sB1 = 0ULL;
                #pragma unroll
                for (int tl = 0; tl < NPAIR; ++tl) {
                    u64 ip = in2[tl];
                    ffma2(sA0, ip, hA2[0][tl]);
                    ffma2(sA1, ip, hA2[1][tl]);
                    ffma2(sB0, ip, hB2[0][tl]);
                    ffma2(sB1, ip, hB2[1][tl]);
                }
                ffma2(acc2[0][0], pack2(v0.x, v0.x), sA0);
                ffma2(acc2[0][1], pack2(v1.x, v1.x), sA1);
                ffma2(acc2[1][0], pack2(v0.y, v0.y), sB0);
                ffma2(acc2[1][1], pack2(v1.y, v1.y), sB1);
            }
        }

        // ---- Epilogue: horizontal add of packed partials, coalesced STG.64 ----
        float* op = out + (((size_t)b * CC + c) * HOo + yA) * WOo + xA;
        #pragma unroll
        for (int yy = 0; yy < RYY; ++yy) {
            float aLo, aHi, bLo, bHi;
            unpack2(acc2[0][yy], aLo, aHi);
            unpack2(acc2[1][yy], bLo, bHi);
            float2 o2 = make_float2(aLo + aHi, bLo + bHi);
            *reinterpret_cast<float2*>(op + (size_t)yy * WOo) = o2;
        }
    }
}

extern "C" void kernel_launch(void* const* d_in, const int* in_sizes, int n_in,
                              void* d_out, int out_size)
{
    // Identify 'input' by element count; keep relative order of vertical/horizontal.
    const int input_elems = BB * CC * HIN * WIN;   // 1,895,064
    int idx_in = 0;
    for (int i = 0; i < n_in; ++i)
        if (in_sizes[i] == input_elems) { idx_in = i; break; }
    int idx_v = -1, idx_h = -1;
    for (int i = 0; i < n_in; ++i) {
        if (i == idx_in) continue;
        if (idx_v < 0) idx_v = i; else if (idx_h < 0) idx_h = i;
    }

    const float* inp  = (const float*)d_in[idx_in];
    const float* vert = (const float*)d_in[idx_v];
    const float* horz = (const float*)d_in[idx_h];
    float* o = (float*)d_out;

    dim3 block(TXX, WYY, 1);
    dim3 grid(WOo / TW, HOo / TYY, BB);   // (8, 64, 2)
    sepconv_kernel<<<grid, block>>>(inp, vert, horz, o);
}

// round 8
// speedup vs baseline: 1.4495x; 1.4495x over previous
#include <cuda_runtime.h>
#include <cstddef>

// Problem constants (fixed by the dataset)
#define Fk   51
#define HOo  512
#define WOo  512
#define CC   3
#define HIN  562   // HO + F - 1
#define WIN  562
#define BB   2
#define HW   (HOo * WOo)

// Tiling: each thread computes 2 x-cols x 2 y-rows. Block = 32x4 threads
// -> output tile 64 wide x 8 tall. ALL 3 channels resident in smem.
#define TXX  32
#define WYY  4
#define RXX  2
#define RYY  2
#define TW   (TXX * RXX)        // 64 output cols per block
#define TYY  (WYY * RYY)        // 8 output rows per block
#define TROWS (TYY + Fk - 1)    // 58 input rows
#define TCOLS 114               // cols 0..113 used (2*31 + 51 = 113); even stride
#define TILE_ELEMS (TROWS * TCOLS)     // 6612
#define SMEM_FLOATS (CC * TILE_ELEMS)  // 19836 -> 79344 bytes

#define NPAIR 13                // tap pairs per half (2 x 13 = 26 pairs = taps 0..51)

typedef unsigned long long u64;

// ---- packed f32x2 helpers (Blackwell FFMA2 path) ----
__device__ __forceinline__ u64 pack2(float lo, float hi) {
    u64 r;
    asm("mov.b64 %0, {%1, %2};" : "=l"(r) : "f"(lo), "f"(hi));
    return r;
}
__device__ __forceinline__ void unpack2(u64 v, float& lo, float& hi) {
    asm("mov.b64 {%0, %1}, %2;" : "=f"(lo), "=f"(hi) : "l"(v));
}
__device__ __forceinline__ void ffma2(u64& d, u64 a, u64 b) {
    asm("fma.rn.f32x2 %0, %1, %2, %0;" : "+l"(d) : "l"(a), "l"(b));
}
__device__ __forceinline__ float2 ldg2(const float* p) {
    return __ldg(reinterpret_cast<const float2*>(p));
}

__global__ __launch_bounds__(TXX * WYY, 2)
void sepconv_kernel(const float* __restrict__ inp,
                    const float* __restrict__ vert,
                    const float* __restrict__ horz,
                    float* __restrict__ out)
{
    extern __shared__ float tile[];   // [CC][TROWS][TCOLS]

    const int b   = blockIdx.z;
    const int x0  = blockIdx.x * TW;
    const int y0  = blockIdx.y * TYY;
    const int tx  = threadIdx.x;
    const int ty  = threadIdx.y;
    const int tid = ty * TXX + tx;

    const int xA = x0 + 2 * tx;      // thread's even column (and xA+1)
    const int yA = y0 + ty * RYY;    // thread's rows yA, yA+1

    // filter bases: layout [b, tap, y, x]
    const float* h_base = horz + (size_t)b * Fk * HW + (size_t)yA * WOo + xA;
    const float* v_base = vert + (size_t)b * Fk * HW + (size_t)yA * WOo + xA;

    // ---- Load ALL 3 channel tiles once (fully in-bounds: col<=113 -> x<=561) ----
    {
        const float* gsrc = inp + ((size_t)b * CC * HIN + y0) * WIN + x0;
        #pragma unroll 1
        for (int idx = tid; idx < SMEM_FLOATS; idx += TXX * WYY) {
            int c   = idx / TILE_ELEMS;
            int rem = idx - c * TILE_ELEMS;
            int r   = rem / TCOLS;
            int col = rem - r * TCOLS;
            tile[idx] = gsrc[((size_t)c * HIN + r) * WIN + col];
        }
    }
    __syncthreads();

    // accumulators: [channel][col A/B][row yy], packed {even-chain, odd-chain}
    u64 acc[CC][RXX][RYY];
    #pragma unroll
    for (int c = 0; c < CC; ++c)
        #pragma unroll
        for (int cx = 0; cx < RXX; ++cx)
            #pragma unroll
            for (int yy = 0; yy < RYY; ++yy) acc[c][cx][yy] = 0ULL;

    #pragma unroll 1
    for (int half = 0; half < 2; ++half) {
        const int T0 = half * NPAIR;   // global pair offset (0 or 13)

        // ---- Pack this half's horizontal taps ONCE (reused by all 3 channels) ----
        // col A (x=xA):   pair T -> {h[2T],   h[2T+1]}  (h[51] := 0)
        // col B (x=xA+1): pair T -> {h[2T-1], h[2T]}    (h[-1] := 0)
        u64 hA2[RYY][NPAIR], hB2[RYY][NPAIR];
        #pragma unroll
        for (int yy = 0; yy < RYY; ++yy) {
            const float* hp = h_base + (size_t)yy * WOo;
            #pragma unroll
            for (int tl = 0; tl < NPAIR; ++tl) {
                int T = T0 + tl;
                float2 gm = (2 * T - 1 >= 0) ? ldg2(hp + (size_t)(2 * T - 1) * HW)
                                             : make_float2(0.f, 0.f);
                float2 gc = ldg2(hp + (size_t)(2 * T) * HW);       // 2T <= 50 always
                float2 gp = (2 * T + 1 < Fk) ? ldg2(hp + (size_t)(2 * T + 1) * HW)
                                             : make_float2(0.f, 0.f);
                hA2[yy][tl] = pack2(gc.x, gp.x);
                hB2[yy][tl] = pack2(gm.y, gc.y);
            }
        }

        const int rowoff = (ty * RYY) * TCOLS + 2 * tx + 2 * T0;

        #pragma unroll 1
        for (int rr = 0; rr < Fk + RYY - 1; ++rr) {   // 52 input rows
            // vertical weights for both columns; issued here, consumed ~200 instrs later
            float2 v0 = (rr <= Fk - 1) ? ldg2(v_base + (size_t)rr * HW)
                                       : make_float2(0.f, 0.f);
            float2 v1 = (rr >= 1)      ? ldg2(v_base + (size_t)(rr - 1) * HW + WOo)
                                       : make_float2(0.f, 0.f);

            // 12 independent packed dot-product chains (3 channels x 4)
            u64 s[CC][4];
            #pragma unroll
            for (int c = 0; c < CC; ++c)
                { s[c][0] = 0ULL; s[c][1] = 0ULL; s[c][2] = 0ULL; s[c][3] = 0ULL; }

            #pragma unroll
            for (int c = 0; c < CC; ++c) {
                const u64* rp = reinterpret_cast<const u64*>(
                    tile + c * TILE_ELEMS + rr * TCOLS + rowoff);
                #pragma unroll
                for (int tl = 0; tl < NPAIR; ++tl) {
                    u64 ip = rp[tl];                 // aligned LDS.64
                    ffma2(s[c][0], ip, hA2[0][tl]);
                    ffma2(s[c][1], ip, hA2[1][tl]);
                    ffma2(s[c][2], ip, hB2[0][tl]);
                    ffma2(s[c][3], ip, hB2[1][tl]);
                }
            }

            // apply vertical weights (v LDGs have had ~200 instrs to land)
            u64 v0x = pack2(v0.x, v0.x), v1x = pack2(v1.x, v1.x);
            u64 v0y = pack2(v0.y, v0.y), v1y = pack2(v1.y, v1.y);
            #pragma unroll
            for (int c = 0; c < CC; ++c) {
                ffma2(acc[c][0][0], v0x, s[c][0]);
                ffma2(acc[c][0][1], v1x, s[c][1]);
                ffma2(acc[c][1][0], v0y, s[c][2]);
                ffma2(acc[c][1][1], v1y, s[c][3]);
            }
        }
    }

    // ---- Epilogue: horizontal add of packed partials, coalesced STG.64 ----
    #pragma unroll
    for (int c = 0; c < CC; ++c) {
        float* op = out + (((size_t)b * CC + c) * HOo + yA) * WOo + xA;
        #pragma unroll
        for (int yy = 0; yy < RYY; ++yy) {
            float aLo, aHi, bLo, bHi;
            unpack2(acc[c][0][yy], aLo, aHi);
            unpack2(acc[c][1][yy], bLo, bHi);
            *reinterpret_cast<float2*>(op + (size_t)yy * WOo)
                = make_float2(aLo + aHi, bLo + bHi);
        }
    }
}

extern "C" void kernel_launch(void* const* d_in, const int* in_sizes, int n_in,
                              void* d_out, int out_size)
{
    // Identify 'input' by element count; keep relative order of vertical/horizontal.
    const int input_elems = BB * CC * HIN * WIN;   // 1,895,064
    int idx_in = 0;
    for (int i = 0; i < n_in; ++i)
        if (in_sizes[i] == input_elems) { idx_in = i; break; }
    int idx_v = -1, idx_h = -1;
    for (int i = 0; i < n_in; ++i) {
        if (i == idx_in) continue;
        if (idx_v < 0) idx_v = i; else if (idx_h < 0) idx_h = i;
    }

    const float* inp  = (const float*)d_in[idx_in];
    const float* vert = (const float*)d_in[idx_v];
    const float* horz = (const float*)d_in[idx_h];
    float* o = (float*)d_out;

    const int smem_bytes = SMEM_FLOATS * (int)sizeof(float);   // 79344
    cudaFuncSetAttribute(sepconv_kernel,
                         cudaFuncAttributeMaxDynamicSharedMemorySize, smem_bytes);

    dim3 block(TXX, WYY, 1);
    dim3 grid(WOo / TW, HOo / TYY, BB);   // (8, 64, 2)
    sepconv_kernel<<<grid, block, smem_bytes>>>(inp, vert, horz, o);
}

// round 9
// speedup vs baseline: 1.7884x; 1.2337x over previous
#include <cuda_runtime.h>
#include <cstddef>

// Problem constants (fixed by the dataset)
#define Fk   51
#define HOo  512
#define WOo  512
#define CC   3
#define HIN  562   // HO + F - 1
#define WIN  562
#define BB   2
#define HW   (HOo * WOo)

// Tiling: each thread computes 2 x-cols x 2 y-rows. Block = 32x6 threads
// -> output tile 64 wide x 12 tall. ALL 3 channels resident in smem.
#define TXX  32
#define WYY  6
#define RXX  2
#define RYY  2
#define TW   (TXX * RXX)        // 64 output cols per block
#define TYY  (WYY * RYY)        // 12 output rows per block
#define NTHREADS (TXX * WYY)    // 192
#define TROWS (TYY + Fk - 1)    // 62 input rows
#define TCOLS 114               // cols 0..113 used (2*31 + 51 = 113); even stride
#define TILE_ELEMS (TROWS * TCOLS)     // 7068
#define SMEM_FLOATS (CC * TILE_ELEMS)  // 21204 -> 84816 bytes

typedef unsigned long long u64;

// ---- packed f32x2 helpers (Blackwell FFMA2 path) ----
__device__ __forceinline__ u64 pack2(float lo, float hi) {
    u64 r;
    asm("mov.b64 %0, {%1, %2};" : "=l"(r) : "f"(lo), "f"(hi));
    return r;
}
__device__ __forceinline__ void unpack2(u64 v, float& lo, float& hi) {
    asm("mov.b64 {%0, %1}, %2;" : "=f"(lo), "=f"(hi) : "l"(v));
}
__device__ __forceinline__ void ffma2(u64& d, u64 a, u64 b) {
    asm("fma.rn.f32x2 %0, %1, %2, %0;" : "+l"(d) : "l"(a), "l"(b));
}
__device__ __forceinline__ float2 ldg2(const float* p) {
    return __ldg(reinterpret_cast<const float2*>(p));
}

// Process one group of P tap-pairs (pairs T0 .. T0+P-1).
// Keeps only 4*P u64 h-registers live -> fits the 168-reg cap at 12 warps/SM.
template<int P>
__device__ __forceinline__ void process_group(
    int T0,
    const float* __restrict__ h_base,
    const float* __restrict__ v_base,
    const float* __restrict__ tile,
    int rowoff,
    u64 (&acc)[CC][RXX][RYY])
{
    // col A (x=xA):   pair T -> {h[2T],   h[2T+1]}  (h[51] := 0)
    // col B (x=xA+1): pair T -> {h[2T-1], h[2T]}    (h[-1] := 0)
    u64 hA2[RYY][P], hB2[RYY][P];
    #pragma unroll
    for (int yy = 0; yy < RYY; ++yy) {
        const float* hp = h_base + (size_t)yy * WOo;
        #pragma unroll
        for (int tl = 0; tl < P; ++tl) {
            int T = T0 + tl;
            float2 gm = (2 * T - 1 >= 0) ? ldg2(hp + (size_t)(2 * T - 1) * HW)
                                         : make_float2(0.f, 0.f);
            float2 gc = ldg2(hp + (size_t)(2 * T) * HW);       // 2T <= 50 always
            float2 gp = (2 * T + 1 < Fk) ? ldg2(hp + (size_t)(2 * T + 1) * HW)
                                         : make_float2(0.f, 0.f);
            hA2[yy][tl] = pack2(gc.x, gp.x);
            hB2[yy][tl] = pack2(gm.y, gc.y);
        }
    }

    const float* base = tile + rowoff + 2 * T0;

    #pragma unroll 1
    for (int rr = 0; rr < Fk + RYY - 1; ++rr) {   // 52 input rows
        // vertical weights for both columns; issued early, consumed at loop end
        float2 v0 = (rr <= Fk - 1) ? ldg2(v_base + (size_t)rr * HW)
                                   : make_float2(0.f, 0.f);
        float2 v1 = (rr >= 1)      ? ldg2(v_base + (size_t)(rr - 1) * HW + WOo)
                                   : make_float2(0.f, 0.f);

        // 12 independent packed dot-product chains (3 channels x 4)
        u64 s[CC][4];
        #pragma unroll
        for (int c = 0; c < CC; ++c)
            { s[c][0] = 0ULL; s[c][1] = 0ULL; s[c][2] = 0ULL; s[c][3] = 0ULL; }

        #pragma unroll
        for (int c = 0; c < CC; ++c) {
            const u64* rp = reinterpret_cast<const u64*>(
                base + c * TILE_ELEMS + rr * TCOLS);
            #pragma unroll
            for (int tl = 0; tl < P; ++tl) {
                u64 ip = rp[tl];                 // aligned LDS.64
                ffma2(s[c][0], ip, hA2[0][tl]);
                ffma2(s[c][1], ip, hA2[1][tl]);
                ffma2(s[c][2], ip, hB2[0][tl]);
                ffma2(s[c][3], ip, hB2[1][tl]);
            }
        }

        u64 v0x = pack2(v0.x, v0.x), v1x = pack2(v1.x, v1.x);
        u64 v0y = pack2(v0.y, v0.y), v1y = pack2(v1.y, v1.y);
        #pragma unroll
        for (int c = 0; c < CC; ++c) {
            ffma2(acc[c][0][0], v0x, s[c][0]);
            ffma2(acc[c][0][1], v1x, s[c][1]);
            ffma2(acc[c][1][0], v0y, s[c][2]);
            ffma2(acc[c][1][1], v1y, s[c][3]);
        }
    }
}

__global__ __launch_bounds__(NTHREADS, 2)
void sepconv_kernel(const float* __restrict__ inp,
                    const float* __restrict__ vert,
                    const float* __restrict__ horz,
                    float* __restrict__ out)
{
    extern __shared__ float tile[];   // [CC][TROWS][TCOLS]

    const int b   = blockIdx.z;
    const int x0  = blockIdx.x * TW;
    const int y0  = blockIdx.y * TYY;
    const int tx  = threadIdx.x;
    const int ty  = threadIdx.y;
    const int tid = ty * TXX + tx;

    const int xA = x0 + 2 * tx;                       // thread's even column (and xA+1)
    int yA = y0 + ty * RYY;                           // nominal rows yA, yA+1
    if (yA > HOo - RYY) yA = HOo - RYY;               // ragged-edge clamp (duplicate work, benign)

    // filter bases: layout [b, tap, y, x]
    const float* h_base = horz + (size_t)b * Fk * HW + (size_t)yA * WOo + xA;
    const float* v_base = vert + (size_t)b * Fk * HW + (size_t)yA * WOo + xA;

    // ---- Load ALL 3 channel tiles once (row-clamped for the last y-block) ----
    {
        const float* gsrc = inp + ((size_t)b * CC * HIN) * WIN + x0;
        #pragma unroll 1
        for (int idx = tid; idx < SMEM_FLOATS; idx += NTHREADS) {
            int c   = idx / TILE_ELEMS;
            int rem = idx - c * TILE_ELEMS;
            int r   = rem / TCOLS;
            int col = rem - r * TCOLS;
            int gr  = y0 + r; if (gr > HIN - 1) gr = HIN - 1;   // clamped rows never read
            tile[idx] = gsrc[((size_t)c * HIN + gr) * WIN + col];
        }
    }
    __syncthreads();

    // accumulators: [channel][col A/B][row yy], packed {even-chain, odd-chain}
    u64 acc[CC][RXX][RYY];
    #pragma unroll
    for (int c = 0; c < CC; ++c)
        #pragma unroll
        for (int cx = 0; cx < RXX; ++cx)
            #pragma unroll
            for (int yy = 0; yy < RYY; ++yy) acc[c][cx][yy] = 0ULL;

    const int rowoff = (yA - y0) * TCOLS + 2 * tx;

    // 26 tap pairs (taps 0..51, h[51]:=0) in 4 register-bounded groups
    process_group<7>( 0, h_base, v_base, tile, rowoff, acc);
    process_group<7>( 7, h_base, v_base, tile, rowoff, acc);
    process_group<7>(14, h_base, v_base, tile, rowoff, acc);
    process_group<5>(21, h_base, v_base, tile, rowoff, acc);

    // ---- Epilogue: horizontal add of packed partials, coalesced STG.64 ----
    #pragma unroll
    for (int c = 0; c < CC; ++c) {
        float* op = out + (((size_t)b * CC + c) * HOo + yA) * WOo + xA;
        #pragma unroll
        for (int yy = 0; yy < RYY; ++yy) {
            float aLo, aHi, bLo, bHi;
            unpack2(acc[c][0][yy], aLo, aHi);
            unpack2(acc[c][1][yy], bLo, bHi);
            *reinterpret_cast<float2*>(op + (size_t)yy * WOo)
                = make_float2(aLo + aHi, bLo + bHi);
        }
    }
}

extern "C" void kernel_launch(void* const* d_in, const int* in_sizes, int n_in,
                              void* d_out, int out_size)
{
    // Identify 'input' by element count; keep relative order of vertical/horizontal.
    const int input_elems = BB * CC * HIN * WIN;   // 1,895,064
    int idx_in = 0;
    for (int i = 0; i < n_in; ++i)
        if (in_sizes[i] == input_elems) { idx_in = i; break; }
    int idx_v = -1, idx_h = -1;
    for (int i = 0; i < n_in; ++i) {
        if (i == idx_in) continue;
        if (idx_v < 0) idx_v = i; else if (idx_h < 0) idx_h = i;
    }

    const float* inp  = (const float*)d_in[idx_in];
    const float* vert = (const float*)d_in[idx_v];
    const float* horz = (const float*)d_in[idx_h];
    float* o = (float*)d_out;

    const int smem_bytes = SMEM_FLOATS * (int)sizeof(float);   // 84816
    cudaFuncSetAttribute(sepconv_kernel,
                         cudaFuncAttributeMaxDynamicSharedMemorySize, smem_bytes);

    dim3 block(TXX, WYY, 1);
    dim3 grid(WOo / TW, (HOo + TYY - 1) / TYY, BB);   // (8, 43, 2)
    sepconv_kernel<<<grid, block, smem_bytes>>>(inp, vert, horz, o);
}

// round 11
// speedup vs baseline: 2.1973x; 1.2286x over previous
#include <cuda_runtime.h>
#include <cstddef>

// Problem constants (fixed by the dataset)
#define Fk   51
#define HOo  512
#define WOo  512
#define CC   3
#define HIN  562   // HO + F - 1
#define WIN  562
#define BB   2
#define HW   (HOo * WOo)

// Tiling: each thread computes 2 x-cols x 2 y-rows. Block = 32x8 threads
// -> output tile 64 wide x 16 tall. ALL 3 channels resident in smem.
// 2 CTAs/SM = 16 warps/SM (regs 256*128*2 = full RF, smem 2*90.3KB < 228KB).
#define TXX  32
#define WYY  8
#define RXX  2
#define RYY  2
#define TW   (TXX * RXX)        // 64 output cols per block
#define TYY  (WYY * RYY)        // 16 output rows per block (512 % 16 == 0, no ragged edge)
#define NTHREADS (TXX * WYY)    // 256
#define TROWS (TYY + Fk - 1)    // 66 input rows
#define TCOLS 114               // cols 0..113 used (2*31 + 51 = 113); even stride
#define TILE_ELEMS (TROWS * TCOLS)     // 7524
#define SMEM_FLOATS (CC * TILE_ELEMS)  // 22572 -> 90288 bytes

typedef unsigned long long u64;

// ---- packed f32x2 helpers (Blackwell FFMA2 path) ----
__device__ __forceinline__ u64 pack2(float lo, float hi) {
    u64 r;
    asm("mov.b64 %0, {%1, %2};" : "=l"(r) : "f"(lo), "f"(hi));
    return r;
}
__device__ __forceinline__ void unpack2(u64 v, float& lo, float& hi) {
    asm("mov.b64 {%0, %1}, %2;" : "=f"(lo), "=f"(hi) : "l"(v));
}
__device__ __forceinline__ void ffma2(u64& d, u64 a, u64 b) {
    asm("fma.rn.f32x2 %0, %1, %2, %0;" : "+l"(d) : "l"(a), "l"(b));
}
__device__ __forceinline__ float2 ldg2(const float* p) {
    return __ldg(reinterpret_cast<const float2*>(p));
}

// Process one group of P tap-pairs (pairs T0 .. T0+P-1).
// Keeps only 4*P u64 h-registers live -> fits the 128-reg cap at 16 warps/SM.
template<int P>
__device__ __forceinline__ void process_group(
    int T0,
    const float* __restrict__ h_base,
    const float* __restrict__ v_base,
    const float* __restrict__ tile,
    int rowoff,
    u64 (&acc)[CC][RXX][RYY])
{
    // col A (x=xA):   pair T -> {h[2T],   h[2T+1]}  (h[51] := 0)
    // col B (x=xA+1): pair T -> {h[2T-1], h[2T]}    (h[-1] := 0)
    u64 hA2[RYY][P], hB2[RYY][P];
    #pragma unroll
    for (int yy = 0; yy < RYY; ++yy) {
        const float* hp = h_base + (size_t)yy * WOo;
        #pragma unroll
        for (int tl = 0; tl < P; ++tl) {
            int T = T0 + tl;
            float2 gm = (2 * T - 1 >= 0) ? ldg2(hp + (size_t)(2 * T - 1) * HW)
                                         : make_float2(0.f, 0.f);
            float2 gc = ldg2(hp + (size_t)(2 * T) * HW);       // 2T <= 50 always
            float2 gp = (2 * T + 1 < Fk) ? ldg2(hp + (size_t)(2 * T + 1) * HW)
                                         : make_float2(0.f, 0.f);
            hA2[yy][tl] = pack2(gc.x, gp.x);
            hB2[yy][tl] = pack2(gm.y, gc.y);
        }
    }

    const float* base = tile + rowoff + 2 * T0;

    #pragma unroll 1
    for (int rr = 0; rr < Fk + RYY - 1; ++rr) {   // 52 input rows
        // vertical weights for both columns; issued early, consumed at loop end
        float2 v0 = (rr <= Fk - 1) ? ldg2(v_base + (size_t)rr * HW)
                                   : make_float2(0.f, 0.f);
        float2 v1 = (rr >= 1)      ? ldg2(v_base + (size_t)(rr - 1) * HW + WOo)
                                   : make_float2(0.f, 0.f);

        // 12 independent packed dot-product chains (3 channels x 4)
        u64 s[CC][4];
        #pragma unroll
        for (int c = 0; c < CC; ++c) {
            s[c][0] = 0ULL; s[c][1] = 0ULL; s[c][2] = 0ULL; s[c][3] = 0ULL;
            const u64* rp = reinterpret_cast<const u64*>(
                base + c * TILE_ELEMS + rr * TCOLS);
            #pragma unroll
            for (int tl = 0; tl < P; ++tl) {
                u64 ip = rp[tl];                 // aligned LDS.64
                ffma2(s[c][0], ip, hA2[0][tl]);
                ffma2(s[c][1], ip, hA2[1][tl]);
                ffma2(s[c][2], ip, hB2[0][tl]);
                ffma2(s[c][3], ip, hB2[1][tl]);
            }
        }

        u64 v0x = pack2(v0.x, v0.x), v1x = pack2(v1.x, v1.x);
        u64 v0y = pack2(v0.y, v0.y), v1y = pack2(v1.y, v1.y);
        #pragma unroll
        for (int c = 0; c < CC; ++c) {
            ffma2(acc[c][0][0], v0x, s[c][0]);
            ffma2(acc[c][0][1], v1x, s[c][1]);
            ffma2(acc[c][1][0], v0y, s[c][2]);
            ffma2(acc[c][1][1], v1y, s[c][3]);
        }
    }
}

__global__ __launch_bounds__(NTHREADS, 2)
void sepconv_kernel(const float* __restrict__ inp,
                    const float* __restrict__ vert,
                    const float* __restrict__ horz,
                    float* __restrict__ out)
{
    extern __shared__ float tile[];   // [CC][TROWS][TCOLS]

    const int b   = blockIdx.z;
    const int x0  = blockIdx.x * TW;
    const int y0  = blockIdx.y * TYY;
    const int tx  = threadIdx.x;
    const int ty  = threadIdx.y;
    const int tid = ty * TXX + tx;

    const int xA = x0 + 2 * tx;      // thread's even column (and xA+1)
    const int yA = y0 + ty * RYY;    // thread's rows yA, yA+1 (no ragged edge: 512%16==0)

    // filter bases: layout [b, tap, y, x]
    const float* h_base = horz + (size_t)b * Fk * HW + (size_t)yA * WOo + xA;
    const float* v_base = vert + (size_t)b * Fk * HW + (size_t)yA * WOo + xA;

    // ---- Load ALL 3 channel tiles once (fully in-bounds: max row 561, max col x 561) ----
    {
        const float* gsrc = inp + ((size_t)b * CC * HIN + y0) * WIN + x0;
        #pragma unroll 1
        for (int idx = tid; idx < SMEM_FLOATS; idx += NTHREADS) {
            int c   = idx / TILE_ELEMS;
            int rem = idx - c * TILE_ELEMS;
            int r   = rem / TCOLS;
            int col = rem - r * TCOLS;
            tile[idx] = gsrc[((size_t)c * HIN + r) * WIN + col];
        }
    }
    __syncthreads();

    // accumulators: [channel][col A/B][row yy], packed {even-chain, odd-chain}
    u64 acc[CC][RXX][RYY];
    #pragma unroll
    for (int c = 0; c < CC; ++c)
        #pragma unroll
        for (int cx = 0; cx < RXX; ++cx)
            #pragma unroll
            for (int yy = 0; yy < RYY; ++yy) acc[c][cx][yy] = 0ULL;

    const int rowoff = (ty * RYY) * TCOLS + 2 * tx;

    // 26 tap pairs (taps 0..51, h[51]:=0) in 4 register-bounded groups
    process_group<7>( 0, h_base, v_base, tile, rowoff, acc);
    process_group<7>( 7, h_base, v_base, tile, rowoff, acc);
    process_group<7>(14, h_base, v_base, tile, rowoff, acc);
    process_group<5>(21, h_base, v_base, tile, rowoff, acc);

    // ---- Epilogue: horizontal add of packed partials, coalesced STG.64 ----
    #pragma unroll
    for (int c = 0; c < CC; ++c) {
        float* op = out + (((size_t)b * CC + c) * HOo + yA) * WOo + xA;
        #pragma unroll
        for (int yy = 0; yy < RYY; ++yy) {
            float aLo, aHi, bLo, bHi;
            unpack2(acc[c][0][yy], aLo, aHi);
            unpack2(acc[c][1][yy], bLo, bHi);
            *reinterpret_cast<float2*>(op + (size_t)yy * WOo)
                = make_float2(aLo + aHi, bLo + bHi);
        }
    }
}

extern "C" void kernel_launch(void* const* d_in, const int* in_sizes, int n_in,
                              void* d_out, int out_size)
{
    // Identify 'input' by element count; keep relative order of vertical/horizontal.
    const int input_elems = BB * CC * HIN * WIN;   // 1,895,064
    int idx_in = 0;
    for (int i = 0; i < n_in; ++i)
        if (in_sizes[i] == input_elems) { idx_in = i; break; }
    int idx_v = -1, idx_h = -1;
    for (int i = 0; i < n_in; ++i) {
        if (i == idx_in) continue;
        if (idx_v < 0) idx_v = i; else if (idx_h < 0) idx_h = i;
    }

    const float* inp  = (const float*)d_in[idx_in];
    const float* vert = (const float*)d_in[idx_v];
    const float* horz = (const float*)d_in[idx_h];
    float* o = (float*)d_out;

    const int smem_bytes = SMEM_FLOATS * (int)sizeof(float);   // 90288
    cudaFuncSetAttribute(sepconv_kernel,
                         cudaFuncAttributeMaxDynamicSharedMemorySize, smem_bytes);

    dim3 block(TXX, WYY, 1);
    dim3 grid(WOo / TW, HOo / TYY, BB);   // (8, 32, 2) = 512 blocks
    sepconv_kernel<<<grid, block, smem_bytes>>>(inp, vert, horz, o);
}